// round 16
// baseline (speedup 1.0000x reference)
#include <cuda_runtime.h>
#include <cuda_fp16.h>
#include <math.h>
#include <stdint.h>

// Problem constants
#define BB 32
#define TT 32
#define AD 32
#define HID 1536
#define K2 (2*HID)   // 3072

// Scratch (__device__ globals)
__device__ __half g_xf[BB*TT*K2];    // concat([a_emb, tau]) fp16
__device__ __half g_hf[BB*TT*HID];   // swish hidden fp16
__device__ int g_gcat[32];
__device__ int g_gsamp[32][2];
__device__ int g_ngroups;

// ---------------------------------------------------------------------------
// Setup: group samples by cat in pairs. One warp.
// ---------------------------------------------------------------------------
__global__ void setup_groups(const int* __restrict__ cats)
{
    int t = threadIdx.x;
    int myc = cats[t];
    unsigned mask = 0;
    #pragma unroll
    for (int s = 0; s < 32; s++) {
        int cs = __shfl_sync(0xffffffffu, myc, s);
        if (cs == t) mask |= (1u << s);
    }
    int cnt = __popc(mask);
    int ng  = (cnt + 1) >> 1;

    int incl = ng;
    #pragma unroll
    for (int off = 1; off < 32; off <<= 1) {
        int v = __shfl_up_sync(0xffffffffu, incl, off);
        if (t >= off) incl += v;
    }
    int pre   = incl - ng;
    int total = __shfl_sync(0xffffffffu, incl, 31);
    if (t == 0) g_ngroups = total;

    unsigned m = mask;
    for (int g = 0; g < ng; g++) {
        int slot = pre + g;
        g_gcat[slot] = t;
        #pragma unroll
        for (int j = 0; j < 2; j++) {
            int s = -1;
            if (m) { s = __ffs(m) - 1; m &= m - 1; }
            g_gsamp[slot][j] = s;
        }
    }
    for (int slot = total + t; slot < 32; slot += 32) {
        g_gcat[slot] = -1;
        g_gsamp[slot][0] = -1;
        g_gsamp[slot][1] = -1;
    }
}

// ---------------------------------------------------------------------------
// Kernel 1: x = [actions @ W1[cat] + b1, sinusoidal(ts)] -> fp16
// ---------------------------------------------------------------------------
__global__ __launch_bounds__(256) void embed_kernel(
    const float* __restrict__ actions,
    const int*   __restrict__ timesteps,
    const int*   __restrict__ cats,
    const float* __restrict__ W1,
    const float* __restrict__ b1)
{
    int b = blockIdx.x;
    int p = blockIdx.y * 256 + threadIdx.x;
    int j = 2 * p;

    __shared__ float sa[TT*AD];
    for (int i = threadIdx.x; i < TT*AD; i += 256)
        sa[i] = actions[(size_t)b*TT*AD + i];
    __syncthreads();

    int cat = cats[b];
    const float* Wc = W1 + (size_t)cat * AD * HID;
    float2 bb = *reinterpret_cast<const float2*>(&b1[(size_t)cat*HID + j]);

    float2 wv[AD];
    #pragma unroll
    for (int k = 0; k < AD; k++)
        wv[k] = *reinterpret_cast<const float2*>(&Wc[(size_t)k*HID + j]);

    const float C = -9.210340371976184f / 768.0f;
    float ts = (float)timesteps[b];
    float freq = expf(C * (float)p);
    float s, c;
    sincosf(ts * freq, &s, &c);
    __half2 tp = __floats2half2_rn(s, c);
    uint32_t tu = *reinterpret_cast<uint32_t*>(&tp);

    #pragma unroll 4
    for (int t = 0; t < TT; t++) {
        float a0 = bb.x, a1 = bb.y;
        #pragma unroll
        for (int k = 0; k < AD; k++) {
            float av = sa[t*AD + k];
            a0 += av * wv[k].x;
            a1 += av * wv[k].y;
        }
        size_t row = (size_t)(b*TT + t) * K2;
        __half2 ap = __floats2half2_rn(a0, a1);
        *reinterpret_cast<uint32_t*>(&g_xf[row + j]) = *reinterpret_cast<uint32_t*>(&ap);
        *reinterpret_cast<uint32_t*>(&g_xf[row + HID + j]) = tu;
    }
}

// ---------------------------------------------------------------------------
// Grouped fp16 mma.sync GEMM, GN=64, prefetch-distance-3 pipeline.
// CTA: M=64 (2 samples, one cat) x N=64, K-tile 32. 8 warps, warp = 32r x 16c.
// One combined {W,X} cp.async group per tile; rings X x4, WF x3, WC x2.
// iter it: wait_group 1 (group it+1 arrived; it+2 may fly); sync;
//          issue it+3; convert(it+1) || compute(it).
// smem 54272 B -> 4 CTAs/SM.
// ---------------------------------------------------------------------------
#define GN    64
#define PADX  40
#define PADW  72
#define OX(s)   ((s)*5120)                      // 4 x 5120  -> [0, 20480)
#define OWF(s)  (20480 + (s)*8192)              // 3 x 8192  -> [20480, 45056)
#define OWC(s)  (45056 + (s)*4608)              // 2 x 4608  -> [45056, 54272)
#define SMEM_BYTES 54272

#define MMA_F16(d, a0,a1,a2,a3, b0,b1) \
  asm volatile("mma.sync.aligned.m16n8k16.row.col.f32.f16.f16.f32 " \
               "{%0,%1,%2,%3}, {%4,%5,%6,%7}, {%8,%9}, {%0,%1,%2,%3};" \
               : "+f"(d[0]),"+f"(d[1]),"+f"(d[2]),"+f"(d[3]) \
               : "r"(a0),"r"(a1),"r"(a2),"r"(a3),"r"(b0),"r"(b1))

#define LDSM_X4(r0,r1,r2,r3, addr) \
  asm volatile("ldmatrix.sync.aligned.m8n8.x4.shared.b16 {%0,%1,%2,%3}, [%4];" \
               : "=r"(r0),"=r"(r1),"=r"(r2),"=r"(r3) : "r"(addr))

#define LDSM_X2T(r0,r1, addr) \
  asm volatile("ldmatrix.sync.aligned.m8n8.x2.trans.shared.b16 {%0,%1}, [%2];" \
               : "=r"(r0),"=r"(r1) : "r"(addr))

#define CP16(sa, ga, sz) \
  asm volatile("cp.async.ca.shared.global [%0], [%1], 16, %2;" \
               :: "r"(sa), "l"(ga), "r"(sz))
#define CP16F(sa, ga) \
  asm volatile("cp.async.ca.shared.global [%0], [%1], 16;" :: "r"(sa), "l"(ga))
#define CP_COMMIT() asm volatile("cp.async.commit_group;" ::: "memory")

__global__ __launch_bounds__(256,4) void gemm_grouped(
    const __half* __restrict__ Xf,
    const float* __restrict__ W,
    const float* __restrict__ bias,
    float* __restrict__ Yf32,
    int K, int writeH)
{
    if ((int)blockIdx.y >= g_ngroups) return;

    extern __shared__ char smem[];
    uint32_t sb;
    asm("{ .reg .u64 t; cvta.to.shared.u64 t, %1; cvt.u32.u64 %0, t; }"
        : "=r"(sb) : "l"(smem));

    int slot = blockIdx.y;
    int cat  = g_gcat[slot];
    int s0 = g_gsamp[slot][0];
    int s1 = g_gsamp[slot][1];

    int n0 = blockIdx.x * GN;

    int tid  = threadIdx.x;
    int lane = tid & 31;
    int warp = tid >> 5;
    int mrow = warp & 1;      // sample half: rows mrow*32..+31
    int ncol = warp >> 1;     // 16-col slice: cols ncol*16..+15

    int lr15 = lane & 15;
    int hiK8 = ((lane >> 4) & 1) * 8;
    int mysamp = mrow ? s1 : s0;
    bool active = (mysamp >= 0);

    float acc[2][2][4];
    #pragma unroll
    for (int mt = 0; mt < 2; mt++)
        #pragma unroll
        for (int nt = 0; nt < 2; nt++)
            #pragma unroll
            for (int j = 0; j < 4; j++) acc[mt][nt][j] = 0.0f;

    // X: 64 rows x 32 k fp16 = 256 x 16B chunks, 1/thread
    int xrl = tid >> 2;
    int xsp = (xrl < 32) ? s0 : s1;
    uint32_t xsz = (xsp >= 0) ? 16 : 0;
    const __half* xg = Xf
        + (size_t)((xsp >= 0) ? (xsp*32 + (xrl & 31)) : 0) * K + (tid & 3) * 8;
    uint32_t xso = (uint32_t)(xrl*(PADX*2) + (tid & 3)*16);

    // W fp32: 32 k x 64 n = 512 x 16B chunks, 2/thread.
    // chunk c: idx = c*256+tid -> kr = idx>>4 (0..31), cn = idx&15
    int wk0 = tid >> 4, wn0 = tid & 15;        // c=0: rows 0..15
    // c=1: rows 16..31, same cn pattern
    const float* wg = W + (size_t)cat * K * HID + (size_t)wk0 * HID + n0 + wn0*4;
    const size_t wc1off = (size_t)16 * HID;    // +16 rows for chunk 1
    const size_t wstep  = (size_t)32 * HID;    // per k-tile advance
    uint32_t wfo = (uint32_t)(wk0*256 + wn0*16);     // + c*4096
    uint32_t wco = (uint32_t)(wk0*(PADW*2) + wn0*8); // + c*16*PADW*2

    int NT = K >> 5;

    // ---- prologue: commit tiles 0,1,2 ----
    #pragma unroll
    for (int pi = 0; pi < 3; pi++) {
        CP16F(sb + OWF(pi) + wfo,        wg + pi*wstep);
        CP16F(sb + OWF(pi) + wfo + 4096, wg + pi*wstep + wc1off);
        CP16(sb + OX(pi) + xso, xg + pi*32, xsz);
        CP_COMMIT();
    }
    // tile 0 arrived (1,2 may fly); convert tile 0 -> WC0
    asm volatile("cp.async.wait_group 2;" ::: "memory");
    #pragma unroll
    for (int c = 0; c < 2; c++) {
        float4 v = *reinterpret_cast<const float4*>(smem + OWF(0) + wfo + c*4096);
        __half2 h0 = __floats2half2_rn(v.x, v.y);
        __half2 h1 = __floats2half2_rn(v.z, v.w);
        asm volatile("st.shared.v2.b32 [%0], {%1,%2};"
                     :: "r"(sb + OWC(0) + wco + c*(16*PADW*2)),
                        "r"(*reinterpret_cast<uint32_t*>(&h0)),
                        "r"(*reinterpret_cast<uint32_t*>(&h1)) : "memory");
    }

    #pragma unroll 1
    for (int it = 0; it < NT; it++) {
        int xs = it & 3;
        int cs = it & 1;

        // group(it+1) arrived; group(it+2) may still fly
        if (it + 2 < NT)
            asm volatile("cp.async.wait_group 1;" ::: "memory");
        else
            asm volatile("cp.async.wait_group 0;" ::: "memory");

        __syncthreads();   // prev region done: WC(it&1) visible; old slots free

        // issue tile it+3: WF((it+3)%3), X((it+3)&3)
        if (it + 3 < NT) {
            int tn = it + 3;
            int wfs = tn % 3;
            const float* wsrc = wg + (size_t)tn * wstep;
            CP16F(sb + OWF(wfs) + wfo,        wsrc);
            CP16F(sb + OWF(wfs) + wfo + 4096, wsrc + wc1off);
            CP16(sb + OX(tn & 3) + xso, xg + (tn << 5), xsz);
            CP_COMMIT();
        }

        // convert tile it+1 (independent of compute below)
        if (it + 1 < NT) {
            int nf = (it + 1) % 3;
            int nc = (it + 1) & 1;
            #pragma unroll
            for (int c = 0; c < 2; c++) {
                float4 v = *reinterpret_cast<const float4*>(smem + OWF(nf) + wfo + c*4096);
                __half2 h0 = __floats2half2_rn(v.x, v.y);
                __half2 h1 = __floats2half2_rn(v.z, v.w);
                asm volatile("st.shared.v2.b32 [%0], {%1,%2};"
                             :: "r"(sb + OWC(nc) + wco + c*(16*PADW*2)),
                                "r"(*reinterpret_cast<uint32_t*>(&h0)),
                                "r"(*reinterpret_cast<uint32_t*>(&h1)) : "memory");
            }
        }

        // compute tile it: warp 32x16, 2 k16 steps
        if (active) {
            #pragma unroll
            for (int ks = 0; ks < 2; ks++) {
                uint32_t a[2][4];
                #pragma unroll
                for (int mt = 0; mt < 2; mt++) {
                    uint32_t aoff = (uint32_t)(OX(xs)
                        + ((mrow*32 + mt*16 + lr15)*PADX + ks*16 + hiK8) * 2);
                    LDSM_X4(a[mt][0],a[mt][1],a[mt][2],a[mt][3], sb + aoff);
                }
                #pragma unroll
                for (int nt = 0; nt < 2; nt++) {
                    uint32_t boff = (uint32_t)(OWC(cs)
                        + ((ks*16 + lr15)*PADW + ncol*16 + nt*8) * 2);
                    uint32_t b0, b1;
                    LDSM_X2T(b0, b1, sb + boff);
                    #pragma unroll
                    for (int mt = 0; mt < 2; mt++)
                        MMA_F16(acc[mt][nt], a[mt][0],a[mt][1],a[mt][2],a[mt][3], b0,b1);
                }
            }
        }
    }

    // ---- epilogue ----
    if (!active) return;
    int r  = lane >> 2;
    int c2 = (lane & 3) * 2;
    #pragma unroll
    for (int mt = 0; mt < 2; mt++) {
        int grow0 = mysamp*32 + mt*16 + r;
        #pragma unroll
        for (int nt = 0; nt < 2; nt++) {
            int col = n0 + ncol*16 + nt*8 + c2;
            float2 bv = *reinterpret_cast<const float2*>(&bias[(size_t)cat*HID + col]);
            float y0 = acc[mt][nt][0] + bv.x;
            float y1 = acc[mt][nt][1] + bv.y;
            float y2 = acc[mt][nt][2] + bv.x;
            float y3 = acc[mt][nt][3] + bv.y;
            if (writeH) {
                y0 = y0 / (1.0f + __expf(-y0));
                y1 = y1 / (1.0f + __expf(-y1));
                y2 = y2 / (1.0f + __expf(-y2));
                y3 = y3 / (1.0f + __expf(-y3));
                __half2 p01 = __floats2half2_rn(y0, y1);
                __half2 p23 = __floats2half2_rn(y2, y3);
                *reinterpret_cast<uint32_t*>(&g_hf[(size_t)grow0*HID + col])
                    = *reinterpret_cast<uint32_t*>(&p01);
                *reinterpret_cast<uint32_t*>(&g_hf[(size_t)(grow0+8)*HID + col])
                    = *reinterpret_cast<uint32_t*>(&p23);
            } else {
                float2 o01 = {y0, y1};
                float2 o23 = {y2, y3};
                *reinterpret_cast<float2*>(&Yf32[(size_t)grow0*HID + col]) = o01;
                *reinterpret_cast<float2*>(&Yf32[(size_t)(grow0+8)*HID + col]) = o23;
            }
        }
    }
}

// ---------------------------------------------------------------------------
extern "C" void kernel_launch(void* const* d_in, const int* in_sizes, int n_in,
                              void* d_out, int out_size)
{
    const float* actions   = (const float*)d_in[0];
    const int*   timesteps = (const int*)  d_in[1];
    const int*   cat_ids   = (const int*)  d_in[2];
    const float* W1        = (const float*)d_in[3];
    const float* b1        = (const float*)d_in[4];
    const float* W2        = (const float*)d_in[5];
    const float* b2        = (const float*)d_in[6];
    const float* W3        = (const float*)d_in[7];
    const float* b3        = (const float*)d_in[8];
    float* out = (float*)d_out;

    __half *xf, *hf;
    cudaGetSymbolAddress((void**)&xf, g_xf);
    cudaGetSymbolAddress((void**)&hf, g_hf);

    static bool attr_set = false;
    if (!attr_set) {
        cudaFuncSetAttribute(gemm_grouped,
                             cudaFuncAttributeMaxDynamicSharedMemorySize, SMEM_BYTES);
        attr_set = true;
    }

    setup_groups<<<1, 32>>>(cat_ids);
    embed_kernel<<<dim3(BB, 3), 256>>>(actions, timesteps, cat_ids, W1, b1);

    // h = swish(x @ W2[cat] + b2) -> fp16
    gemm_grouped<<<dim3(HID/GN, 32), 256, SMEM_BYTES>>>(xf, W2, b2, nullptr, K2, 1);

    // out = h @ W3[cat] + b3 -> fp32
    gemm_grouped<<<dim3(HID/GN, 32), 256, SMEM_BYTES>>>(hf, W3, b3, out, HID, 0);
}

// round 17
// speedup vs baseline: 1.7501x; 1.7501x over previous
#include <cuda_runtime.h>
#include <cuda_fp16.h>
#include <math.h>
#include <stdint.h>

// Problem constants
#define BB 32
#define TT 32
#define AD 32
#define HID 1536
#define K2 (2*HID)   // 3072

// Scratch (__device__ globals)
__device__ __half g_xf[BB*TT*K2];    // concat([a_emb, tau]) fp16
__device__ __half g_hf[BB*TT*HID];   // swish hidden fp16
__device__ int g_gcat[32];
__device__ int g_gsamp[32][2];
__device__ int g_ngroups;

// ---------------------------------------------------------------------------
// Setup: group samples by cat in pairs. One warp.
// ---------------------------------------------------------------------------
__global__ void setup_groups(const int* __restrict__ cats)
{
    int t = threadIdx.x;
    int myc = cats[t];
    unsigned mask = 0;
    #pragma unroll
    for (int s = 0; s < 32; s++) {
        int cs = __shfl_sync(0xffffffffu, myc, s);
        if (cs == t) mask |= (1u << s);
    }
    int cnt = __popc(mask);
    int ng  = (cnt + 1) >> 1;

    int incl = ng;
    #pragma unroll
    for (int off = 1; off < 32; off <<= 1) {
        int v = __shfl_up_sync(0xffffffffu, incl, off);
        if (t >= off) incl += v;
    }
    int pre   = incl - ng;
    int total = __shfl_sync(0xffffffffu, incl, 31);
    if (t == 0) g_ngroups = total;

    unsigned m = mask;
    for (int g = 0; g < ng; g++) {
        int slot = pre + g;
        g_gcat[slot] = t;
        #pragma unroll
        for (int j = 0; j < 2; j++) {
            int s = -1;
            if (m) { s = __ffs(m) - 1; m &= m - 1; }
            g_gsamp[slot][j] = s;
        }
    }
    for (int slot = total + t; slot < 32; slot += 32) {
        g_gcat[slot] = -1;
        g_gsamp[slot][0] = -1;
        g_gsamp[slot][1] = -1;
    }
}

// ---------------------------------------------------------------------------
// Kernel 1: x = [actions @ W1[cat] + b1, sinusoidal(ts)] -> fp16
// ---------------------------------------------------------------------------
__global__ __launch_bounds__(256) void embed_kernel(
    const float* __restrict__ actions,
    const int*   __restrict__ timesteps,
    const int*   __restrict__ cats,
    const float* __restrict__ W1,
    const float* __restrict__ b1)
{
    int b = blockIdx.x;
    int p = blockIdx.y * 256 + threadIdx.x;
    int j = 2 * p;

    __shared__ float sa[TT*AD];
    for (int i = threadIdx.x; i < TT*AD; i += 256)
        sa[i] = actions[(size_t)b*TT*AD + i];
    __syncthreads();

    int cat = cats[b];
    const float* Wc = W1 + (size_t)cat * AD * HID;
    float2 bb = *reinterpret_cast<const float2*>(&b1[(size_t)cat*HID + j]);

    float2 wv[AD];
    #pragma unroll
    for (int k = 0; k < AD; k++)
        wv[k] = *reinterpret_cast<const float2*>(&Wc[(size_t)k*HID + j]);

    const float C = -9.210340371976184f / 768.0f;
    float ts = (float)timesteps[b];
    float freq = expf(C * (float)p);
    float s, c;
    sincosf(ts * freq, &s, &c);
    __half2 tp = __floats2half2_rn(s, c);
    uint32_t tu = *reinterpret_cast<uint32_t*>(&tp);

    #pragma unroll 4
    for (int t = 0; t < TT; t++) {
        float a0 = bb.x, a1 = bb.y;
        #pragma unroll
        for (int k = 0; k < AD; k++) {
            float av = sa[t*AD + k];
            a0 += av * wv[k].x;
            a1 += av * wv[k].y;
        }
        size_t row = (size_t)(b*TT + t) * K2;
        __half2 ap = __floats2half2_rn(a0, a1);
        *reinterpret_cast<uint32_t*>(&g_xf[row + j]) = *reinterpret_cast<uint32_t*>(&ap);
        *reinterpret_cast<uint32_t*>(&g_xf[row + HID + j]) = tu;
    }
}

// ---------------------------------------------------------------------------
// Shared GEMM pieces: CTA M=64 x N=128, K-tile 32, 8 warps (warp = 32r x 32c).
// ---------------------------------------------------------------------------
#define GN    128
#define PADX  40
#define PADW  136

#define MMA_F16(d, a0,a1,a2,a3, b0,b1) \
  asm volatile("mma.sync.aligned.m16n8k16.row.col.f32.f16.f16.f32 " \
               "{%0,%1,%2,%3}, {%4,%5,%6,%7}, {%8,%9}, {%0,%1,%2,%3};" \
               : "+f"(d[0]),"+f"(d[1]),"+f"(d[2]),"+f"(d[3]) \
               : "r"(a0),"r"(a1),"r"(a2),"r"(a3),"r"(b0),"r"(b1))

#define LDSM_X4(r0,r1,r2,r3, addr) \
  asm volatile("ldmatrix.sync.aligned.m8n8.x4.shared.b16 {%0,%1,%2,%3}, [%4];" \
               : "=r"(r0),"=r"(r1),"=r"(r2),"=r"(r3) : "r"(addr))

#define LDSM_X2T(r0,r1, addr) \
  asm volatile("ldmatrix.sync.aligned.m8n8.x2.trans.shared.b16 {%0,%1}, [%2];" \
               : "=r"(r0),"=r"(r1) : "r"(addr))

#define CP16(sa, ga, sz) \
  asm volatile("cp.async.ca.shared.global [%0], [%1], 16, %2;" \
               :: "r"(sa), "l"(ga), "r"(sz))
#define CP16F(sa, ga) \
  asm volatile("cp.async.ca.shared.global [%0], [%1], 16;" :: "r"(sa), "l"(ga))
#define CP_COMMIT() asm volatile("cp.async.commit_group;" ::: "memory")

#define CONVERT_W(srcbase, dstbase) \
  do { \
    _Pragma("unroll") \
    for (int c = 0; c < 4; c++) { \
        float4 v = *reinterpret_cast<const float4*>(smem + (srcbase) + wfo + c*4096); \
        __half2 h0 = __floats2half2_rn(v.x, v.y); \
        __half2 h1 = __floats2half2_rn(v.z, v.w); \
        asm volatile("st.shared.v2.b32 [%0], {%1,%2};" \
                     :: "r"(sb + (dstbase) + wco + c*(8*PADW*2)), \
                        "r"(*reinterpret_cast<uint32_t*>(&h0)), \
                        "r"(*reinterpret_cast<uint32_t*>(&h1)) : "memory"); \
    } \
  } while (0)

#define COMPUTE_TILE(oxbase, owcbase) \
  do { \
    _Pragma("unroll") \
    for (int ks = 0; ks < 2; ks++) { \
        uint32_t a[2][4]; \
        _Pragma("unroll") \
        for (int mt = 0; mt < 2; mt++) { \
            uint32_t aoff = (uint32_t)((oxbase) \
                + ((mrow*32 + mt*16 + lr15)*PADX + ks*16 + hiK8) * 2); \
            LDSM_X4(a[mt][0],a[mt][1],a[mt][2],a[mt][3], sb + aoff); \
        } \
        _Pragma("unroll") \
        for (int nt = 0; nt < 4; nt++) { \
            uint32_t boff = (uint32_t)((owcbase) \
                + ((ks*16 + lr15)*PADW + ncol*32 + nt*8) * 2); \
            uint32_t b0, b1; \
            LDSM_X2T(b0, b1, sb + boff); \
            _Pragma("unroll") \
            for (int mt = 0; mt < 2; mt++) \
                MMA_F16(acc[mt][nt], a[mt][0],a[mt][1],a[mt][2],a[mt][3], b0,b1); \
        } \
    } \
  } while (0)

#define GEMM_PREAMBLE \
    extern __shared__ char smem[]; \
    uint32_t sb; \
    asm("{ .reg .u64 t; cvta.to.shared.u64 t, %1; cvt.u32.u64 %0, t; }" \
        : "=r"(sb) : "l"(smem)); \
    int slot = blockIdx.y; \
    int cat  = g_gcat[slot]; \
    int s0 = g_gsamp[slot][0]; \
    int s1 = g_gsamp[slot][1]; \
    int n0 = blockIdx.x * GN; \
    int tid  = threadIdx.x; \
    int lane = tid & 31; \
    int warp = tid >> 5; \
    int mrow = warp & 1; \
    int ncol = warp >> 1; \
    int lr15 = lane & 15; \
    int hiK8 = ((lane >> 4) & 1) * 8; \
    int mysamp = mrow ? s1 : s0; \
    bool active = (mysamp >= 0); \
    float acc[2][4][4]; \
    _Pragma("unroll") \
    for (int mt = 0; mt < 2; mt++) \
        _Pragma("unroll") \
        for (int nt = 0; nt < 4; nt++) \
            _Pragma("unroll") \
            for (int j = 0; j < 4; j++) acc[mt][nt][j] = 0.0f; \
    int xrl = tid >> 2; \
    int xsp = (xrl < 32) ? s0 : s1; \
    uint32_t xsz = (xsp >= 0) ? 16 : 0; \
    const __half* xg = Xf \
        + (size_t)((xsp >= 0) ? (xsp*32 + (xrl & 31)) : 0) * K + (tid & 3) * 8; \
    uint32_t xso = (uint32_t)(xrl*(PADX*2) + (tid & 3)*16); \
    const float* wg = W + (size_t)cat * K * HID + (size_t)warp * HID + n0 + lane*4; \
    const size_t wrstep = (size_t)8 * HID; \
    const size_t wstep  = (size_t)32 * HID; \
    uint32_t wfo = (uint32_t)(warp*512 + lane*16); \
    uint32_t wco = (uint32_t)(warp*(PADW*2) + lane*8); \
    int NT = K >> 5;

#define GEMM_EPILOGUE \
    if (!active) return; \
    int r  = lane >> 2; \
    int c2 = (lane & 3) * 2; \
    _Pragma("unroll") \
    for (int mt = 0; mt < 2; mt++) { \
        int grow0 = mysamp*32 + mt*16 + r; \
        _Pragma("unroll") \
        for (int nt = 0; nt < 4; nt++) { \
            int col = n0 + ncol*32 + nt*8 + c2; \
            float2 bv = *reinterpret_cast<const float2*>(&bias[(size_t)cat*HID + col]); \
            float y0 = acc[mt][nt][0] + bv.x; \
            float y1 = acc[mt][nt][1] + bv.y; \
            float y2 = acc[mt][nt][2] + bv.x; \
            float y3 = acc[mt][nt][3] + bv.y; \
            if (writeH) { \
                y0 = y0 / (1.0f + __expf(-y0)); \
                y1 = y1 / (1.0f + __expf(-y1)); \
                y2 = y2 / (1.0f + __expf(-y2)); \
                y3 = y3 / (1.0f + __expf(-y3)); \
                __half2 p01 = __floats2half2_rn(y0, y1); \
                __half2 p23 = __floats2half2_rn(y2, y3); \
                *reinterpret_cast<uint32_t*>(&g_hf[(size_t)grow0*HID + col]) \
                    = *reinterpret_cast<uint32_t*>(&p01); \
                *reinterpret_cast<uint32_t*>(&g_hf[(size_t)(grow0+8)*HID + col]) \
                    = *reinterpret_cast<uint32_t*>(&p23); \
            } else { \
                float2 o01 = {y0, y1}; \
                float2 o23 = {y2, y3}; \
                *reinterpret_cast<float2*>(&Yf32[(size_t)grow0*HID + col]) = o01; \
                *reinterpret_cast<float2*>(&Yf32[(size_t)(grow0+8)*HID + col]) = o23; \
            } \
        } \
    }

// ---------------------------------------------------------------------------
// Variant A (R12 schedule): dist-2, serialized convert. smem 65536, 3 CTA/SM.
// Best for DRAM-heavy K=3072 (GEMM2).
// ---------------------------------------------------------------------------
#define A_OX(s)   ((s)*5120)                 // 3 x 5120
#define A_OWF(s)  (15360 + (s)*16384)        // 2 x 16384
#define A_OWC(s)  (48128 + (s)*8704)         // 2 x 8704
#define A_SMEM 65536

__global__ __launch_bounds__(256,3) void gemm_a(
    const __half* __restrict__ Xf,
    const float* __restrict__ W,
    const float* __restrict__ bias,
    float* __restrict__ Yf32,
    int K, int writeH)
{
    if ((int)blockIdx.y >= g_ngroups) return;
    GEMM_PREAMBLE

    // prologue: tiles 0,1
    #pragma unroll
    for (int pi = 0; pi < 2; pi++) {
        CP16(sb + A_OX(pi) + xso, xg + pi*32, xsz);
        #pragma unroll
        for (int c = 0; c < 4; c++)
            CP16F(sb + A_OWF(pi) + wfo + c*4096, wg + pi*wstep + c*wrstep);
        CP_COMMIT();
    }

    #pragma unroll 1
    for (int it = 0; it < NT; it++) {
        int xs = it % 3;
        int cs = it & 1;

        if (it < NT - 1)
            asm volatile("cp.async.wait_group 1;" ::: "memory");
        else
            asm volatile("cp.async.wait_group 0;" ::: "memory");

        CONVERT_W(A_OWF(cs), A_OWC(cs));
        __syncthreads();

        if (it + 2 < NT) {
            int k0 = (it + 2) << 5;
            CP16(sb + A_OX((it + 2) % 3) + xso, xg + k0, xsz);
            const float* wsrc = wg + (size_t)(it + 2) * wstep;
            #pragma unroll
            for (int c = 0; c < 4; c++)
                CP16F(sb + A_OWF(cs) + wfo + c*4096, wsrc + c*wrstep);
            CP_COMMIT();
        }

        if (active) COMPUTE_TILE(A_OX(xs), A_OWC(cs));
    }

    GEMM_EPILOGUE
}

// ---------------------------------------------------------------------------
// Variant B (R15 schedule): dist-3, decoupled convert. smem 87040, 2 CTA/SM.
// Best for K=1536 (GEMM3).
// ---------------------------------------------------------------------------
#define B_OX(s)   ((s)*5120)                 // 4 x 5120
#define B_OWF(s)  (20480 + (s)*16384)        // 3 x 16384
#define B_OWC(s)  (69632 + (s)*8704)         // 2 x 8704
#define B_SMEM 87040

__global__ __launch_bounds__(256,2) void gemm_b(
    const __half* __restrict__ Xf,
    const float* __restrict__ W,
    const float* __restrict__ bias,
    float* __restrict__ Yf32,
    int K, int writeH)
{
    if ((int)blockIdx.y >= g_ngroups) return;
    GEMM_PREAMBLE

    // prologue: tiles 0,1,2
    #pragma unroll
    for (int pi = 0; pi < 3; pi++) {
        #pragma unroll
        for (int c = 0; c < 4; c++)
            CP16F(sb + B_OWF(pi) + wfo + c*4096, wg + pi*wstep + c*wrstep);
        CP16(sb + B_OX(pi) + xso, xg + pi*32, xsz);
        CP_COMMIT();
    }
    asm volatile("cp.async.wait_group 2;" ::: "memory");
    CONVERT_W(B_OWF(0), B_OWC(0));

    #pragma unroll 1
    for (int it = 0; it < NT; it++) {
        int xs = it & 3;
        int cs = it & 1;

        if (it + 2 < NT)
            asm volatile("cp.async.wait_group 1;" ::: "memory");
        else
            asm volatile("cp.async.wait_group 0;" ::: "memory");

        __syncthreads();

        if (it + 3 < NT) {
            int tn = it + 3;
            int wfs = tn % 3;
            const float* wsrc = wg + (size_t)tn * wstep;
            #pragma unroll
            for (int c = 0; c < 4; c++)
                CP16F(sb + B_OWF(wfs) + wfo + c*4096, wsrc + c*wrstep);
            CP16(sb + B_OX(tn & 3) + xso, xg + (tn << 5), xsz);
            CP_COMMIT();
        }

        if (it + 1 < NT) {
            int nf = (it + 1) % 3;
            int nc = (it + 1) & 1;
            CONVERT_W(B_OWF(nf), B_OWC(nc));
        }

        if (active) COMPUTE_TILE(B_OX(xs), B_OWC(cs));
    }

    GEMM_EPILOGUE
}

// ---------------------------------------------------------------------------
extern "C" void kernel_launch(void* const* d_in, const int* in_sizes, int n_in,
                              void* d_out, int out_size)
{
    const float* actions   = (const float*)d_in[0];
    const int*   timesteps = (const int*)  d_in[1];
    const int*   cat_ids   = (const int*)  d_in[2];
    const float* W1        = (const float*)d_in[3];
    const float* b1        = (const float*)d_in[4];
    const float* W2        = (const float*)d_in[5];
    const float* b2        = (const float*)d_in[6];
    const float* W3        = (const float*)d_in[7];
    const float* b3        = (const float*)d_in[8];
    float* out = (float*)d_out;

    __half *xf, *hf;
    cudaGetSymbolAddress((void**)&xf, g_xf);
    cudaGetSymbolAddress((void**)&hf, g_hf);

    static bool attr_set = false;
    if (!attr_set) {
        cudaFuncSetAttribute(gemm_a,
                             cudaFuncAttributeMaxDynamicSharedMemorySize, A_SMEM);
        cudaFuncSetAttribute(gemm_b,
                             cudaFuncAttributeMaxDynamicSharedMemorySize, B_SMEM);
        attr_set = true;
    }

    setup_groups<<<1, 32>>>(cat_ids);
    embed_kernel<<<dim3(BB, 3), 256>>>(actions, timesteps, cat_ids, W1, b1);

    // h = swish(x @ W2[cat] + b2) -> fp16   (variant A: occupancy-favoring)
    gemm_a<<<dim3(HID/GN, 32), 256, A_SMEM>>>(xf, W2, b2, nullptr, K2, 1);

    // out = h @ W3[cat] + b3 -> fp32        (variant B: deep pipeline)
    gemm_b<<<dim3(HID/GN, 32), 256, B_SMEM>>>(hf, W3, b3, out, HID, 0);
}